// round 2
// baseline (speedup 1.0000x reference)
#include <cuda_runtime.h>
#include <cstdint>

#define DINL __device__ __forceinline__

// ---------------- problem constants ----------------
static constexpr int L   = 128;  // rows per operand tile (M and N)
static constexpr int D   = 768;  // reduction dim
static constexpr int KC  = 32;   // fp32 elements per K-chunk
static constexpr int NCH = D / KC;  // 24 chunks

// smem layout: padded row stride of 36 floats kills bank conflicts for both
// the mma fragment LDS pattern and the cp.async STS pattern.
static constexpr int RS = 36;                        // row stride in floats
static constexpr int TILE_FLOATS  = L * RS;          // 4608 floats = 18 KB
static constexpr int STAGE_FLOATS = 2 * TILE_FLOATS; // A + B
static constexpr int HDR_FLOATS   = 272;             // rowmax[256] + wsum[8] + pad
static constexpr uint32_t SMEM_DYN =
    (HDR_FLOATS + 2 * STAGE_FLOATS) * sizeof(float); // 1088 + 73728 = 74816 B

// ---------------- PTX helpers ----------------
DINL uint32_t smem_u32(const void* p) {
    uint32_t a;
    asm("{ .reg .u64 t; cvta.to.shared.u64 t, %1; cvt.u32.u64 %0, t; }" : "=r"(a) : "l"(p));
    return a;
}
DINL void cp_async16(uint32_t dst, const void* src) {
    asm volatile("cp.async.cg.shared.global [%0], [%1], 16;" :: "r"(dst), "l"(src) : "memory");
}
DINL void cp_commit() { asm volatile("cp.async.commit_group;" ::: "memory"); }
DINL void cp_wait1()  { asm volatile("cp.async.wait_group 1;" ::: "memory"); }
DINL void cp_wait0()  { asm volatile("cp.async.wait_group 0;" ::: "memory"); }

DINL void mma_tf32(float* d, const uint32_t* a, const uint32_t* b) {
    asm volatile(
        "mma.sync.aligned.m16n8k8.row.col.f32.tf32.tf32.f32 "
        "{%0,%1,%2,%3}, {%4,%5,%6,%7}, {%8,%9}, {%0,%1,%2,%3};\n"
        : "+f"(d[0]), "+f"(d[1]), "+f"(d[2]), "+f"(d[3])
        : "r"(a[0]), "r"(a[1]), "r"(a[2]), "r"(a[3]), "r"(b[0]), "r"(b[1]));
}

// ---------------- kernel ----------------
// One CTA per (b,k) pair. sim = ctx @ ent^T via tf32 mma.sync in registers;
// out[pair] = sum over rows of rowwise max of sim.
__global__ void __launch_bounds__(256, 2)
som_kernel(const float* __restrict__ in, float* __restrict__ out) {
    extern __shared__ float smem[];
    float* rowbuf = smem;            // [2][128] rowwise maxima (per col-half)
    float* wsum   = smem + 256;      // [8]
    float* tiles  = smem + HDR_FLOATS;

    const int tid  = threadIdx.x;
    const int wid  = tid >> 5;
    const int lane = tid & 31;
    const int wr   = wid & 3;   // warp row  (rows  wr*32 .. wr*32+31)
    const int wc   = wid >> 2;  // warp col  (cols  wc*64 .. wc*64+63)

    const size_t pair = blockIdx.x;
    const float* ctx = in + pair * (size_t)(2 * L * D);
    const float* ent = ctx + (size_t)(L * D);

    // ---- cp.async plan: 8x 16B transfers per thread per chunk (4 A + 4 B) ----
    const int lrow = tid >> 3;  // 0..31
    const int lseg = tid & 7;   // 0..7 (16B units within the 128B K-chunk row)
    const uint32_t tiles_a = smem_u32(tiles);

    uint32_t dstA[4], dstB[4];
    const float* srcA[4];
    const float* srcB[4];
#pragma unroll
    for (int i = 0; i < 4; i++) {
        int r = lrow + 32 * i;
        uint32_t off = (uint32_t)(r * RS + lseg * 4) * 4u;
        dstA[i] = tiles_a + off;
        dstB[i] = tiles_a + (uint32_t)TILE_FLOATS * 4u + off;
        srcA[i] = ctx + (size_t)r * D + lseg * 4;
        srcB[i] = ent + (size_t)r * D + lseg * 4;
    }

    // ---- accumulators: 2 m-tiles x 8 n-tiles x 4 regs ----
    float acc[2][8][4];
#pragma unroll
    for (int mt = 0; mt < 2; mt++)
#pragma unroll
        for (int nt = 0; nt < 8; nt++)
#pragma unroll
            for (int r = 0; r < 4; r++) acc[mt][nt][r] = 0.0f;

    // fragment LDS base indices
    const int qid  = lane >> 2;   // 0..7
    const int qlan = lane & 3;    // 0..3

    // prologue: load chunk 0 into stage 0
    {
        const uint32_t sb = 0;
#pragma unroll
        for (int i = 0; i < 4; i++) {
            cp_async16(dstA[i] + sb, srcA[i]);
            cp_async16(dstB[i] + sb, srcB[i]);
        }
        cp_commit();
    }

#pragma unroll 1
    for (int c = 0; c < NCH; c++) {
        // issue next chunk into the other stage
        if (c + 1 < NCH) {
            const uint32_t sb = (uint32_t)((c + 1) & 1) * STAGE_FLOATS * 4u;
            const int coff = (c + 1) * KC;
#pragma unroll
            for (int i = 0; i < 4; i++) {
                cp_async16(dstA[i] + sb, srcA[i] + coff);
                cp_async16(dstB[i] + sb, srcB[i] + coff);
            }
            cp_commit();
            cp_wait1();
        } else {
            cp_wait0();
        }
        __syncthreads();

        const float* sA = tiles + (size_t)(c & 1) * STAGE_FLOATS;
        const float* sB = sA + TILE_FLOATS;

#pragma unroll
        for (int ks = 0; ks < 4; ks++) {
            const int k0 = ks * 8;
            uint32_t a[2][4], b[8][2];
#pragma unroll
            for (int mt = 0; mt < 2; mt++) {
                const int r0 = wr * 32 + mt * 16 + qid;
                a[mt][0] = __float_as_uint(sA[(r0    ) * RS + k0 + qlan    ]);
                a[mt][1] = __float_as_uint(sA[(r0 + 8) * RS + k0 + qlan    ]);
                a[mt][2] = __float_as_uint(sA[(r0    ) * RS + k0 + qlan + 4]);
                a[mt][3] = __float_as_uint(sA[(r0 + 8) * RS + k0 + qlan + 4]);
            }
#pragma unroll
            for (int nt = 0; nt < 8; nt++) {
                const int n0 = wc * 64 + nt * 8 + qid;
                b[nt][0] = __float_as_uint(sB[n0 * RS + k0 + qlan    ]);
                b[nt][1] = __float_as_uint(sB[n0 * RS + k0 + qlan + 4]);
            }
#pragma unroll
            for (int mt = 0; mt < 2; mt++)
#pragma unroll
                for (int nt = 0; nt < 8; nt++)
                    mma_tf32(acc[mt][nt], a[mt], b[nt]);
        }
        __syncthreads();
    }

    // ---- epilogue: rowwise max over this warp's 64 cols, then combine ----
    // acc reg r holds (row = base + 8*(r>>1), col = col0 + (r&1))
#pragma unroll
    for (int mt = 0; mt < 2; mt++) {
#pragma unroll
        for (int h = 0; h < 2; h++) {
            float m = __int_as_float(0xff800000);
#pragma unroll
            for (int nt = 0; nt < 8; nt++) {
                m = fmaxf(m, acc[mt][nt][2 * h]);
                m = fmaxf(m, acc[mt][nt][2 * h + 1]);
            }
            // reduce across the 4 lanes covering this row's columns
            m = fmaxf(m, __shfl_xor_sync(0xffffffffu, m, 1));
            m = fmaxf(m, __shfl_xor_sync(0xffffffffu, m, 2));
            if (qlan == 0)
                rowbuf[wc * 128 + wr * 32 + mt * 16 + h * 8 + qid] = m;
        }
    }
    __syncthreads();

    if (tid < 128) {
        float v = fmaxf(rowbuf[tid], rowbuf[128 + tid]);
#pragma unroll
        for (int o = 16; o > 0; o >>= 1) v += __shfl_xor_sync(0xffffffffu, v, o);
        if (lane == 0) wsum[wid] = v;
    }
    __syncthreads();
    if (tid == 0) out[pair] = wsum[0] + wsum[1] + wsum[2] + wsum[3];
}

// ---------------- launch ----------------
extern "C" void kernel_launch(void* const* d_in, const int* in_sizes, int n_in,
                              void* d_out, int out_size) {
    const float* in = (const float*)d_in[0];
    float* out = (float*)d_out;
    const int pairs = in_sizes[0] / (2 * L * D);  // B*K = 1024

    cudaFuncSetAttribute(som_kernel, cudaFuncAttributeMaxDynamicSharedMemorySize, SMEM_DYN);
    som_kernel<<<pairs, 256, SMEM_DYN>>>(in, out);
}

// round 4
// speedup vs baseline: 1.5267x; 1.5267x over previous
#include <cuda_runtime.h>
#include <cstdint>

#define DINL __device__ __forceinline__

// ---------------- problem constants ----------------
static constexpr int L   = 128;  // rows per operand tile (M and N)
static constexpr int D   = 768;  // reduction dim
static constexpr int KC  = 32;   // fp32 elements per K-chunk
static constexpr int NCH = D / KC;  // 24 chunks
static constexpr int STAGES = 3;

// smem: padded row stride of 36 floats -> conflict-free LDS and STS patterns
static constexpr int RS = 36;                         // row stride in floats
static constexpr int TILE_FLOATS  = L * RS;           // 4608 floats = 18 KB
static constexpr int STAGE_FLOATS = 2 * TILE_FLOATS;  // A + B = 36 KB
static constexpr int HDR_FLOATS   = 272;              // rowmax[256] + wsum[8] + pad
static constexpr uint32_t TILE_BYTES  = TILE_FLOATS * 4;   // 18432
static constexpr uint32_t STAGE_BYTES = STAGE_FLOATS * 4;  // 36864
static constexpr uint32_t ROWBLK_BYTES = 32 * RS * 4;      // 4608
static constexpr uint32_t SMEM_DYN =
    (HDR_FLOATS + STAGES * STAGE_FLOATS) * sizeof(float);  // 111,680 B

// ---------------- PTX helpers ----------------
DINL uint32_t smem_u32(const void* p) {
    uint32_t a;
    asm("{ .reg .u64 t; cvta.to.shared.u64 t, %1; cvt.u32.u64 %0, t; }" : "=r"(a) : "l"(p));
    return a;
}
DINL void cp_async16(uint32_t dst, const void* src) {
    asm volatile("cp.async.cg.shared.global [%0], [%1], 16;" :: "r"(dst), "l"(src) : "memory");
}
DINL void cp_commit() { asm volatile("cp.async.commit_group;" ::: "memory"); }
DINL void cp_wait1()  { asm volatile("cp.async.wait_group 1;" ::: "memory"); }
DINL void cp_wait0()  { asm volatile("cp.async.wait_group 0;" ::: "memory"); }

DINL void mma_tf32(float* d, const uint32_t* a, const uint32_t* b) {
    asm volatile(
        "mma.sync.aligned.m16n8k8.row.col.f32.tf32.tf32.f32 "
        "{%0,%1,%2,%3}, {%4,%5,%6,%7}, {%8,%9}, {%0,%1,%2,%3};\n"
        : "+f"(d[0]), "+f"(d[1]), "+f"(d[2]), "+f"(d[3])
        : "r"(a[0]), "r"(a[1]), "r"(a[2]), "r"(a[3]), "r"(b[0]), "r"(b[1]));
}

DINL uint32_t f2u(float x) { return __float_as_uint(x); }

// A fragment for this warp's two 16-row m-tiles at k-offset k0.
// pA points at sA + (wr*32+qid)*RS + qlan.
DINL void load_a(uint32_t (&a)[2][4], const float* __restrict__ pA, int k0) {
#pragma unroll
    for (int mt = 0; mt < 2; mt++) {
        const int base = mt * 16 * RS;
        a[mt][0] = f2u(pA[base + k0]);
        a[mt][1] = f2u(pA[base + 8 * RS + k0]);
        a[mt][2] = f2u(pA[base + k0 + 4]);
        a[mt][3] = f2u(pA[base + 8 * RS + k0 + 4]);
    }
}
// B fragments for this warp's eight 8-col n-tiles at k-offset k0.
// pB points at sB + (wc*64+qid)*RS + qlan.
DINL void load_b(uint32_t (&b)[8][2], const float* __restrict__ pB, int k0) {
#pragma unroll
    for (int nt = 0; nt < 8; nt++) {
        b[nt][0] = f2u(pB[nt * 8 * RS + k0]);
        b[nt][1] = f2u(pB[nt * 8 * RS + k0 + 4]);
    }
}

// ---------------- kernel ----------------
// One CTA per (b,k) pair. sim = ctx @ ent^T via tf32 mma.sync in registers;
// out[pair] = sum over rows of rowwise max of sim.
__global__ void __launch_bounds__(256, 2)
som_kernel(const float* __restrict__ in, float* __restrict__ out) {
    extern __shared__ float smem[];
    float* rowbuf = smem;            // [2][128] rowwise maxima (per col-half)
    float* wsum   = smem + 256;      // [8]
    float* tiles  = smem + HDR_FLOATS;

    const int tid  = threadIdx.x;
    const int wid  = tid >> 5;
    const int lane = tid & 31;
    const int wr   = wid & 3;   // warp row  (rows wr*32 .. +31)
    const int wc   = wid >> 2;  // warp col  (cols wc*64 .. +63)
    const int qid  = lane >> 2; // 0..7
    const int qlan = lane & 3;  // 0..3

    const size_t pair = blockIdx.x;
    const float* ctx = in + pair * (size_t)(2 * L * D);

    // ---- cp.async plan: 8x 16B per thread per chunk (4 A-rows + 4 B-rows) ----
    const int lrow = tid >> 3;  // 0..31
    const int lseg = tid & 7;   // 0..7
    const float* gbase = ctx + (size_t)lrow * D + lseg * 4;
    const uint32_t dst0 = smem_u32(tiles) + (uint32_t)(lrow * RS + lseg * 4) * 4u;

    // frag LDS base indices (immediate-offset loads from these)
    const int idxA = (wr * 32 + qid) * RS + qlan;
    const int idxB = (wc * 64 + qid) * RS + qlan;

    // ---- accumulators: 2 m-tiles x 8 n-tiles x 4 regs ----
    float acc[2][8][4];
#pragma unroll
    for (int mt = 0; mt < 2; mt++)
#pragma unroll
        for (int nt = 0; nt < 8; nt++)
#pragma unroll
            for (int r = 0; r < 4; r++) acc[mt][nt][r] = 0.0f;

    // issue cp.async group for chunk c into stage c%3
    auto issue = [&](int c) {
        const float* pa = gbase + c * KC;
        const uint32_t da = dst0 + (uint32_t)(c % STAGES) * STAGE_BYTES;
#pragma unroll
        for (int i = 0; i < 4; i++) {
            cp_async16(da + i * ROWBLK_BYTES, pa + (size_t)i * 32 * D);
            cp_async16(da + TILE_BYTES + i * ROWBLK_BYTES,
                       pa + (size_t)L * D + (size_t)i * 32 * D);
        }
        cp_commit();
    };

    // prologue: chunks 0 and 1 in flight
    issue(0);
    issue(1);

    uint32_t A[2][2][4];
    uint32_t Bf[2][8][2];

#pragma unroll 1
    for (int c = 0; c < NCH; c++) {
        if (c == NCH - 1) cp_wait0(); else cp_wait1();  // my groups for chunk c done
        __syncthreads();  // everyone's chunk-c data visible; chunk c-1 reads all done

        // refill the buffer chunk c-1 used (stage (c+2)%3) — safe after barrier
        if (c + 2 < NCH) issue(c + 2);

        const float* sA = tiles + (size_t)(c % STAGES) * STAGE_FLOATS;
        const float* pA = sA + idxA;
        const float* pB = sA + TILE_FLOATS + idxB;

        load_a(A[0], pA, 0);
        load_b(Bf[0], pB, 0);

#pragma unroll
        for (int ks = 0; ks < 4; ks++) {
            const int cur = ks & 1, nxt = cur ^ 1;
            if (ks < 3) {
                load_a(A[nxt], pA, (ks + 1) * 8);
                load_b(Bf[nxt], pB, (ks + 1) * 8);
            }
#pragma unroll
            for (int mt = 0; mt < 2; mt++)
#pragma unroll
                for (int nt = 0; nt < 8; nt++)
                    mma_tf32(acc[mt][nt], A[cur][mt], Bf[cur][nt]);
        }
    }

    // ---- epilogue: rowwise max over this warp's 64 cols, then combine ----
    // acc reg r holds (row = base + 8*(r>>1), col = col0 + (r&1))
#pragma unroll
    for (int mt = 0; mt < 2; mt++) {
#pragma unroll
        for (int h = 0; h < 2; h++) {
            float m = __int_as_float(0xff800000);
#pragma unroll
            for (int nt = 0; nt < 8; nt++) {
                m = fmaxf(m, acc[mt][nt][2 * h]);
                m = fmaxf(m, acc[mt][nt][2 * h + 1]);
            }
            m = fmaxf(m, __shfl_xor_sync(0xffffffffu, m, 1));
            m = fmaxf(m, __shfl_xor_sync(0xffffffffu, m, 2));
            if (qlan == 0)
                rowbuf[wc * 128 + wr * 32 + mt * 16 + h * 8 + qid] = m;
        }
    }
    __syncthreads();

    if (tid < 128) {
        float v = fmaxf(rowbuf[tid], rowbuf[128 + tid]);
#pragma unroll
        for (int o = 16; o > 0; o >>= 1) v += __shfl_xor_sync(0xffffffffu, v, o);
        if (lane == 0) wsum[wid] = v;
    }
    __syncthreads();
    if (tid == 0) out[pair] = wsum[0] + wsum[1] + wsum[2] + wsum[3];
}

// ---------------- launch ----------------
extern "C" void kernel_launch(void* const* d_in, const int* in_sizes, int n_in,
                              void* d_out, int out_size) {
    const float* in = (const float*)d_in[0];
    float* out = (float*)d_out;
    const int pairs = in_sizes[0] / (2 * L * D);  // B*K = 1024

    cudaFuncSetAttribute(som_kernel, cudaFuncAttributeMaxDynamicSharedMemorySize, SMEM_DYN);
    som_kernel<<<pairs, 256, SMEM_DYN>>>(in, out);
}